// round 1
// baseline (speedup 1.0000x reference)
#include <cuda_runtime.h>
#include <math.h>
#include <float.h>

// Problem dimensions (fixed for this problem instance)
#define BB 4
#define NP 16384
#define SP 2048
#define C1P 128
#define C2P 256
#define HP 256
#define MROWS (BB * NP)          // 65536
#define K1P (C1P + C2P)          // 384
#define BN_EPS 1e-5f

// ---------------- scratch (device globals; no allocation allowed) ----------
__device__ float g_x[(size_t)MROWS * K1P];   // concat( points1, interpolated ) : 100 MB
__device__ float g_h[(size_t)MROWS * HP];    // hidden after layer 1            : 67 MB
__device__ int   g_idx[MROWS * 3];
__device__ float g_wt[MROWS * 3];
__device__ float g_s1[HP], g_b1[HP], g_s2[HP], g_b2[HP];

// ---------------- BN param folding: scale = gamma*rsqrt(rv+eps), bias = beta - rm*scale
__global__ void bn_params_kernel(const float* __restrict__ g1, const float* __restrict__ b1,
                                 const float* __restrict__ rm1, const float* __restrict__ rv1,
                                 const float* __restrict__ g2, const float* __restrict__ b2,
                                 const float* __restrict__ rm2, const float* __restrict__ rv2) {
    int h = threadIdx.x;
    if (h < HP) {
        float s1 = g1[h] * rsqrtf(rv1[h] + BN_EPS);
        g_s1[h] = s1;
        g_b1[h] = b1[h] - rm1[h] * s1;
        float s2 = g2[h] * rsqrtf(rv2[h] + BN_EPS);
        g_s2[h] = s2;
        g_b2[h] = b2[h] - rm2[h] * s2;
    }
}

// ---------------- 3-NN search + inverse-distance weights ----------------
// grid: (NP/256, BB), block: 256. One thread per query point.
__global__ void knn3_kernel(const float* __restrict__ xyz1, const float* __restrict__ xyz2) {
    __shared__ float sx[SP], sy[SP], sz[SP], sn[SP];
    const int b = blockIdx.y;
    const float* q = xyz2 + (size_t)b * SP * 3;
    for (int i = threadIdx.x; i < SP; i += blockDim.x) {
        float x = q[i * 3 + 0], y = q[i * 3 + 1], z = q[i * 3 + 2];
        sx[i] = x; sy[i] = y; sz[i] = z;
        sn[i] = x * x + y * y + z * z;
    }
    __syncthreads();

    const int n = blockIdx.x * blockDim.x + threadIdx.x;
    const float* p = xyz1 + ((size_t)b * NP + n) * 3;
    const float px = p[0], py = p[1], pz = p[2];
    const float pn = px * px + py * py + pz * pz;
    const float ax = -2.0f * px, ay = -2.0f * py, az = -2.0f * pz;

    // best0 <= best1 <= best2, values are (d^2 - pn); comparison order invariant.
    float v0 = FLT_MAX, v1 = FLT_MAX, v2 = FLT_MAX;
    int i0 = 0, i1 = 0, i2 = 0;

#pragma unroll 4
    for (int s = 0; s < SP; s++) {
        float t = fmaf(ax, sx[s], sn[s]);
        t = fmaf(ay, sy[s], t);
        t = fmaf(az, sz[s], t);
        if (t < v2) {
            if (t < v1) {
                if (t < v0) {
                    v2 = v1; i2 = i1; v1 = v0; i1 = i0; v0 = t; i0 = s;
                } else {
                    v2 = v1; i2 = i1; v1 = t; i1 = s;
                }
            } else {
                v2 = t; i2 = s;
            }
        }
    }

    // reference: dist = sqrt(max(d2,0)); d = max(dist, 1e-10); w = (1/d)/sum(1/d)
    float d0 = fmaxf(sqrtf(fmaxf(v0 + pn, 0.0f)), 1e-10f);
    float d1 = fmaxf(sqrtf(fmaxf(v1 + pn, 0.0f)), 1e-10f);
    float d2 = fmaxf(sqrtf(fmaxf(v2 + pn, 0.0f)), 1e-10f);
    float w0 = 1.0f / d0, w1 = 1.0f / d1, w2 = 1.0f / d2;
    float inv = 1.0f / (w0 + w1 + w2);

    int base = (b * NP + n) * 3;
    g_idx[base + 0] = i0; g_idx[base + 1] = i1; g_idx[base + 2] = i2;
    g_wt[base + 0] = w0 * inv; g_wt[base + 1] = w1 * inv; g_wt[base + 2] = w2 * inv;
}

// ---------------- interpolate + concat into g_x ----------------
// grid: MROWS blocks, block: K1P (=384) threads. One block per point.
__global__ void interp_concat_kernel(const float* __restrict__ points1,
                                     const float* __restrict__ points2) {
    const int pt = blockIdx.x;          // 0..MROWS-1
    const int b = pt / NP;
    const int t = threadIdx.x;          // 0..383

    __shared__ int si[3];
    __shared__ float sw[3];
    if (t < 3) { si[t] = g_idx[pt * 3 + t]; sw[t] = g_wt[pt * 3 + t]; }
    __syncthreads();

    float v;
    if (t < C1P) {
        v = points1[(size_t)pt * C1P + t];
    } else {
        const int c = t - C1P;
        const float* p2 = points2 + (size_t)b * SP * C2P;
        v = sw[0] * p2[(size_t)si[0] * C2P + c];
        v = fmaf(sw[1], p2[(size_t)si[1] * C2P + c], v);
        v = fmaf(sw[2], p2[(size_t)si[2] * C2P + c], v);
    }
    g_x[(size_t)pt * K1P + t] = v;
}

// ---------------- fused GEMM (out = A @ W^T) + BN + ReLU ----------------
// A: [M, K] row-major.  W: [H, K] row-major.  out: [M, H].
// Tile 64x64, BK=16, 256 threads, 4x4 micro-tile per thread.
template <int K>
__global__ void __launch_bounds__(256)
gemm_bn_relu_kernel(const float* __restrict__ A, const float* __restrict__ W,
                    const float* __restrict__ scale, const float* __restrict__ bias,
                    float* __restrict__ out) {
    constexpr int BM = 64, BN = 64, BK = 16;
    __shared__ float As[BK][BM];
    __shared__ float Bs[BK][BN];

    const int tid = threadIdx.x;
    const int lr = tid >> 2;            // 0..63  : row within tile (load)
    const int lc = (tid & 3) << 2;      // 0,4,8,12 : k offset (load)
    const int tm = (tid >> 4) << 2;     // 0..60 step 4 : row group (compute)
    const int tn = (tid & 15) << 2;     // 0..60 step 4 : col group (compute)

    const float* aptr = A + (size_t)(blockIdx.x * BM + lr) * K + lc;
    const float* bptr = W + (size_t)(blockIdx.y * BN + lr) * K + lc;

    float acc[4][4];
#pragma unroll
    for (int i = 0; i < 4; i++)
#pragma unroll
        for (int j = 0; j < 4; j++) acc[i][j] = 0.0f;

    for (int k0 = 0; k0 < K; k0 += BK) {
        float4 av = *reinterpret_cast<const float4*>(aptr);
        float4 bv = *reinterpret_cast<const float4*>(bptr);
        aptr += BK;
        bptr += BK;
        As[lc + 0][lr] = av.x; As[lc + 1][lr] = av.y;
        As[lc + 2][lr] = av.z; As[lc + 3][lr] = av.w;
        Bs[lc + 0][lr] = bv.x; Bs[lc + 1][lr] = bv.y;
        Bs[lc + 2][lr] = bv.z; Bs[lc + 3][lr] = bv.w;
        __syncthreads();

#pragma unroll
        for (int k = 0; k < BK; k++) {
            float4 a4 = *reinterpret_cast<const float4*>(&As[k][tm]);
            float4 b4 = *reinterpret_cast<const float4*>(&Bs[k][tn]);
            float ra[4] = {a4.x, a4.y, a4.z, a4.w};
            float rb[4] = {b4.x, b4.y, b4.z, b4.w};
#pragma unroll
            for (int i = 0; i < 4; i++)
#pragma unroll
                for (int j = 0; j < 4; j++)
                    acc[i][j] = fmaf(ra[i], rb[j], acc[i][j]);
        }
        __syncthreads();
    }

    const int gm = blockIdx.x * BM + tm;
    const int gn = blockIdx.y * BN + tn;
    float sc[4], bs[4];
#pragma unroll
    for (int j = 0; j < 4; j++) { sc[j] = scale[gn + j]; bs[j] = bias[gn + j]; }

#pragma unroll
    for (int i = 0; i < 4; i++) {
        float4 o;
        o.x = fmaxf(fmaf(acc[i][0], sc[0], bs[0]), 0.0f);
        o.y = fmaxf(fmaf(acc[i][1], sc[1], bs[1]), 0.0f);
        o.z = fmaxf(fmaf(acc[i][2], sc[2], bs[2]), 0.0f);
        o.w = fmaxf(fmaf(acc[i][3], sc[3], bs[3]), 0.0f);
        *reinterpret_cast<float4*>(out + (size_t)(gm + i) * HP + gn) = o;
    }
}

// ---------------- launch ----------------
extern "C" void kernel_launch(void* const* d_in, const int* in_sizes, int n_in,
                              void* d_out, int out_size) {
    const float* xyz1    = (const float*)d_in[0];
    const float* xyz2    = (const float*)d_in[1];
    const float* points1 = (const float*)d_in[2];
    const float* points2 = (const float*)d_in[3];
    const float* W1      = (const float*)d_in[4];
    const float* gamma1  = (const float*)d_in[5];
    const float* beta1   = (const float*)d_in[6];
    const float* rm1     = (const float*)d_in[7];
    const float* rv1     = (const float*)d_in[8];
    const float* W2      = (const float*)d_in[9];
    const float* gamma2  = (const float*)d_in[10];
    const float* beta2   = (const float*)d_in[11];
    const float* rm2     = (const float*)d_in[12];
    const float* rv2     = (const float*)d_in[13];
    float* out = (float*)d_out;

    float *px, *ph, *ps1, *pb1, *ps2, *pb2;
    cudaGetSymbolAddress((void**)&px,  g_x);
    cudaGetSymbolAddress((void**)&ph,  g_h);
    cudaGetSymbolAddress((void**)&ps1, g_s1);
    cudaGetSymbolAddress((void**)&pb1, g_b1);
    cudaGetSymbolAddress((void**)&ps2, g_s2);
    cudaGetSymbolAddress((void**)&pb2, g_b2);

    bn_params_kernel<<<1, HP>>>(gamma1, beta1, rm1, rv1, gamma2, beta2, rm2, rv2);

    knn3_kernel<<<dim3(NP / 256, BB), 256>>>(xyz1, xyz2);

    interp_concat_kernel<<<MROWS, K1P>>>(points1, points2);

    gemm_bn_relu_kernel<K1P><<<dim3(MROWS / 64, HP / 64), 256>>>(px, W1, ps1, pb1, ph);
    gemm_bn_relu_kernel<HP><<<dim3(MROWS / 64, HP / 64), 256>>>(ph, W2, ps2, pb2, out);
}

// round 6
// speedup vs baseline: 2.4168x; 2.4168x over previous
#include <cuda_runtime.h>
#include <cuda_bf16.h>
#include <math.h>
#include <float.h>
#include <stdint.h>

#define BB 4
#define NP 16384
#define SP 2048
#define C1P 128
#define C2P 256
#define HP 256
#define MROWS (BB * NP)          // 65536
#define K1P 384
#define BN_EPS 1e-5f

// ---------------- device scratch (no allocation allowed) ----------------
__device__ int   g_idx[MROWS * 3];
__device__ float g_wt[MROWS * 3];
__device__ float g_s1[HP], g_b1[HP], g_s2[HP], g_b2[HP];
// weights pre-split to bf16 hi/lo, stored K-MAJOR: [K][H]
__device__ __align__(16) __nv_bfloat16 g_w1h[K1P * HP], g_w1l[K1P * HP];
__device__ __align__(16) __nv_bfloat16 g_w2h[HP * HP],  g_w2l[HP * HP];

// ---------------- mma/ldmatrix helpers (baseline PTX, sm_80+) ----------------
__device__ __forceinline__ void ldsm4(uint32_t& r0, uint32_t& r1, uint32_t& r2, uint32_t& r3,
                                      uint32_t addr) {
    asm volatile("ldmatrix.sync.aligned.m8n8.x4.shared.b16 {%0,%1,%2,%3}, [%4];"
                 : "=r"(r0), "=r"(r1), "=r"(r2), "=r"(r3) : "r"(addr));
}
__device__ __forceinline__ void ldsm4t(uint32_t& r0, uint32_t& r1, uint32_t& r2, uint32_t& r3,
                                       uint32_t addr) {
    asm volatile("ldmatrix.sync.aligned.m8n8.x4.trans.shared.b16 {%0,%1,%2,%3}, [%4];"
                 : "=r"(r0), "=r"(r1), "=r"(r2), "=r"(r3) : "r"(addr));
}
__device__ __forceinline__ void mma16816(float* c, const uint32_t* a, const uint32_t* b) {
    asm volatile("mma.sync.aligned.m16n8k16.row.col.f32.bf16.bf16.f32 "
                 "{%0,%1,%2,%3}, {%4,%5,%6,%7}, {%8,%9}, {%0,%1,%2,%3};"
                 : "+f"(c[0]), "+f"(c[1]), "+f"(c[2]), "+f"(c[3])
                 : "r"(a[0]), "r"(a[1]), "r"(a[2]), "r"(a[3]), "r"(b[0]), "r"(b[1]));
}
__device__ __forceinline__ void split2(float x, float y, uint32_t& hp, uint32_t& lp) {
    __nv_bfloat16 hx = __float2bfloat16(x), hy = __float2bfloat16(y);
    __nv_bfloat16 lx = __float2bfloat16(x - __bfloat162float(hx));
    __nv_bfloat16 ly = __float2bfloat16(y - __bfloat162float(hy));
    hp = ((uint32_t)__bfloat16_as_ushort(hy) << 16) | __bfloat16_as_ushort(hx);
    lp = ((uint32_t)__bfloat16_as_ushort(ly) << 16) | __bfloat16_as_ushort(lx);
}

// ---------------- prep: BN fold + W -> bf16 hi/lo split (k-major) ----------------
__global__ void prep_kernel(const float* __restrict__ W1, const float* __restrict__ W2,
                            const float* __restrict__ g1, const float* __restrict__ be1,
                            const float* __restrict__ rm1, const float* __restrict__ rv1,
                            const float* __restrict__ g2, const float* __restrict__ be2,
                            const float* __restrict__ rm2, const float* __restrict__ rv2) {
    int i = blockIdx.x * blockDim.x + threadIdx.x;
    if (i < HP) {
        float s = g1[i] * rsqrtf(rv1[i] + BN_EPS);
        g_s1[i] = s; g_b1[i] = be1[i] - rm1[i] * s;
        float s2 = g2[i] * rsqrtf(rv2[i] + BN_EPS);
        g_s2[i] = s2; g_b2[i] = be2[i] - rm2[i] * s2;
    }
    if (i < K1P * HP) {                       // i = k*HP + n
        int k = i >> 8, n = i & 255;
        float v = W1[n * K1P + k];
        __nv_bfloat16 h = __float2bfloat16(v);
        g_w1h[i] = h;
        g_w1l[i] = __float2bfloat16(v - __bfloat162float(h));
    }
    if (i < HP * HP) {
        int k = i >> 8, n = i & 255;
        float v = W2[n * HP + k];
        __nv_bfloat16 h = __float2bfloat16(v);
        g_w2h[i] = h;
        g_w2l[i] = __float2bfloat16(v - __bfloat162float(h));
    }
}

// ---------------- 3-NN search + inverse-distance weights ----------------
__global__ void knn3_kernel(const float* __restrict__ xyz1, const float* __restrict__ xyz2) {
    __shared__ float sx[SP], sy[SP], sz[SP], sn[SP];
    const int b = blockIdx.y;
    const float* q = xyz2 + (size_t)b * SP * 3;
    for (int i = threadIdx.x; i < SP; i += blockDim.x) {
        float x = q[i * 3 + 0], y = q[i * 3 + 1], z = q[i * 3 + 2];
        sx[i] = x; sy[i] = y; sz[i] = z;
        sn[i] = x * x + y * y + z * z;
    }
    __syncthreads();

    const int n = blockIdx.x * blockDim.x + threadIdx.x;
    const float* p = xyz1 + ((size_t)b * NP + n) * 3;
    const float px = p[0], py = p[1], pz = p[2];
    const float pn = px * px + py * py + pz * pz;
    const float ax = -2.0f * px, ay = -2.0f * py, az = -2.0f * pz;

    float v0 = FLT_MAX, v1 = FLT_MAX, v2 = FLT_MAX;
    int i0 = 0, i1 = 0, i2 = 0;

#pragma unroll 4
    for (int s = 0; s < SP; s++) {
        float t = fmaf(ax, sx[s], sn[s]);
        t = fmaf(ay, sy[s], t);
        t = fmaf(az, sz[s], t);
        if (t < v2) {
            if (t < v1) {
                if (t < v0) {
                    v2 = v1; i2 = i1; v1 = v0; i1 = i0; v0 = t; i0 = s;
                } else {
                    v2 = v1; i2 = i1; v1 = t; i1 = s;
                }
            } else {
                v2 = t; i2 = s;
            }
        }
    }

    float d0 = fmaxf(sqrtf(fmaxf(v0 + pn, 0.0f)), 1e-10f);
    float d1 = fmaxf(sqrtf(fmaxf(v1 + pn, 0.0f)), 1e-10f);
    float d2 = fmaxf(sqrtf(fmaxf(v2 + pn, 0.0f)), 1e-10f);
    float w0 = 1.0f / d0, w1 = 1.0f / d1, w2 = 1.0f / d2;
    float inv = 1.0f / (w0 + w1 + w2);

    int base = (b * NP + n) * 3;
    g_idx[base + 0] = i0; g_idx[base + 1] = i1; g_idx[base + 2] = i2;
    g_wt[base + 0] = w0 * inv; g_wt[base + 1] = w1 * inv; g_wt[base + 2] = w2 * inv;
}

// ---------------- fused interp + 2-layer MLP via mma.sync bf16x3 ----------------
// SMEM layout (bytes):
#define SM_S1 0
#define SM_B1 1024
#define SM_S2 2048
#define SM_B2 3072
#define SM_SI 4096
#define SM_SW 5632
// A chunk: 128 rows x 32 k bf16, row stride 40 bf16 = 80 B (conflict-free ldmatrix)
#define A_HI 7168
#define A_LO 17408
// W chunk: k-major, 32 k rows x 256 n bf16, row stride 264 bf16 = 528 B
#define W_HI 27648
#define W_LO 44544
// h: 128 rows x 256 k bf16, row stride 264 bf16 = 528 B
#define H_HI 61440
#define H_LO 129024
#define SMEM_BYTES 196608

__global__ void __launch_bounds__(256, 1)
mlp_kernel(const float* __restrict__ points1, const float* __restrict__ points2,
           float* __restrict__ out) {
    extern __shared__ char smem[];
    const int tid = threadIdx.x;
    const int lane = tid & 31, wid = tid >> 5;
    const int wm = wid & 1, wn = wid >> 1;          // warp grid 2(M) x 4(N), tile 64x64
    const int row0 = blockIdx.x * 128;
    const int b = blockIdx.x >> 7;                  // 128 tiles per batch
    const uint32_t sb = (uint32_t)__cvta_generic_to_shared(smem);

    float* s_s1 = (float*)(smem + SM_S1);
    float* s_b1 = (float*)(smem + SM_B1);
    float* s_s2 = (float*)(smem + SM_S2);
    float* s_b2 = (float*)(smem + SM_B2);
    int*   s_si = (int*)(smem + SM_SI);
    float* s_sw = (float*)(smem + SM_SW);

    for (int i = tid; i < HP; i += 256) {
        s_s1[i] = g_s1[i]; s_b1[i] = g_b1[i];
        s_s2[i] = g_s2[i]; s_b2[i] = g_b2[i];
    }
    for (int i = tid; i < 384; i += 256) {
        s_si[i] = g_idx[row0 * 3 + i];
        s_sw[i] = g_wt[row0 * 3 + i];
    }
    __syncthreads();

    float acc[4][8][4];
#pragma unroll
    for (int mt = 0; mt < 4; mt++)
#pragma unroll
        for (int nt = 0; nt < 8; nt++)
#pragma unroll
            for (int j = 0; j < 4; j++) acc[mt][nt][j] = 0.0f;

    const int qmh = ((lane >> 3) & 1) * 8;          // ldmatrix quad: first-half selector
    const int qkh = (lane >> 4) * 8;                // ldmatrix quad: second-half selector
    const int lrow = lane & 7;

    // ================= LAYER 1: K=384, 12 chunks of 32 =================
#pragma unroll 1
    for (int kc = 0; kc < 12; kc++) {
        if (kc) __syncthreads();                    // prior chunk's ldmatrix done
        // ---- build A chunk (hi/lo): thread -> (row, 16-k half-row)
        {
            const int row = tid >> 1, kh = (tid & 1) * 16;
            const int kg = kc * 32 + kh;
            float v[16];
            if (kg < C1P) {
                const float4* s4 = (const float4*)(points1 + (size_t)(row0 + row) * C1P + kg);
#pragma unroll
                for (int q = 0; q < 4; q++) {
                    float4 f = s4[q];
                    v[q * 4] = f.x; v[q * 4 + 1] = f.y; v[q * 4 + 2] = f.z; v[q * 4 + 3] = f.w;
                }
            } else {
                const int c2 = kg - C1P;
                const float* p2 = points2 + (size_t)b * SP * C2P + c2;
                const int ib = row * 3;
                const float w0 = s_sw[ib], w1 = s_sw[ib + 1], w2 = s_sw[ib + 2];
                const float4* q0 = (const float4*)(p2 + (size_t)s_si[ib] * C2P);
                const float4* q1 = (const float4*)(p2 + (size_t)s_si[ib + 1] * C2P);
                const float4* q2 = (const float4*)(p2 + (size_t)s_si[ib + 2] * C2P);
#pragma unroll
                for (int q = 0; q < 4; q++) {
                    float4 f0 = q0[q], f1 = q1[q], f2 = q2[q];
                    v[q * 4]     = fmaf(w2, f2.x, fmaf(w1, f1.x, w0 * f0.x));
                    v[q * 4 + 1] = fmaf(w2, f2.y, fmaf(w1, f1.y, w0 * f0.y));
                    v[q * 4 + 2] = fmaf(w2, f2.z, fmaf(w1, f1.z, w0 * f0.z));
                    v[q * 4 + 3] = fmaf(w2, f2.w, fmaf(w1, f1.w, w0 * f0.w));
                }
            }
#pragma unroll
            for (int i2 = 0; i2 < 8; i2++) {
                uint32_t hp, lp;
                split2(v[2 * i2], v[2 * i2 + 1], hp, lp);
                uint32_t off = row * 80 + (kh + 2 * i2) * 2;
                *(uint32_t*)(smem + A_HI + off) = hp;
                *(uint32_t*)(smem + A_LO + off) = lp;
            }
        }
        // ---- copy W1 chunk (k-major rows of 512B)
        {
            const uint4* gh = (const uint4*)g_w1h;
            const uint4* gl = (const uint4*)g_w1l;
#pragma unroll
            for (int e = tid; e < 1024; e += 256) {
                int r = e >> 5, q = e & 31;
                uint32_t off = r * 528 + q * 16;
                *(uint4*)(smem + W_HI + off) = gh[(kc * 32 + r) * 32 + q];
                *(uint4*)(smem + W_LO + off) = gl[(kc * 32 + r) * 32 + q];
            }
        }
        __syncthreads();
        // ---- mma: 2 k16 sub-tiles
#pragma unroll
        for (int kk = 0; kk < 2; kk++) {
            uint32_t bh[8][2], bl[8][2];
#pragma unroll
            for (int np = 0; np < 4; np++) {
                int n0 = wn * 64 + np * 16;
                uint32_t roff = (uint32_t)(kk * 16 + qmh + lrow) * 528 + (n0 + qkh) * 2;
                ldsm4t(bh[2 * np][0], bh[2 * np][1], bh[2 * np + 1][0], bh[2 * np + 1][1],
                       sb + W_HI + roff);
                ldsm4t(bl[2 * np][0], bl[2 * np][1], bl[2 * np + 1][0], bl[2 * np + 1][1],
                       sb + W_LO + roff);
            }
#pragma unroll
            for (int mt = 0; mt < 4; mt++) {
                int m0 = wm * 64 + mt * 16;
                uint32_t aoff = (uint32_t)(m0 + qmh + lrow) * 80 + (kk * 16 + qkh) * 2;
                uint32_t ah[4], al[4];
                ldsm4(ah[0], ah[1], ah[2], ah[3], sb + A_HI + aoff);
                ldsm4(al[0], al[1], al[2], al[3], sb + A_LO + aoff);
#pragma unroll
                for (int nt = 0; nt < 8; nt++) {
                    mma16816(acc[mt][nt], ah, bh[nt]);
                    mma16816(acc[mt][nt], ah, bl[nt]);
                    mma16816(acc[mt][nt], al, bh[nt]);
                }
            }
        }
    }

    // ================= EPILOGUE 1: BN+ReLU -> h (bf16 hi/lo, smem) =================
#pragma unroll
    for (int mt = 0; mt < 4; mt++)
#pragma unroll
    for (int nt = 0; nt < 8; nt++) {
        int m0 = wm * 64 + mt * 16, n0 = wn * 64 + nt * 8;
        int r0 = m0 + (lane >> 2), n = n0 + 2 * (lane & 3);
        float s0 = s_s1[n], s1v = s_s1[n + 1], b0v = s_b1[n], b1v = s_b1[n + 1];
        float* c = acc[mt][nt];
        float v0 = fmaxf(fmaf(c[0], s0, b0v), 0.0f);
        float v1 = fmaxf(fmaf(c[1], s1v, b1v), 0.0f);
        uint32_t hp, lp;
        split2(v0, v1, hp, lp);
        uint32_t off = r0 * 528 + n * 2;
        *(uint32_t*)(smem + H_HI + off) = hp;
        *(uint32_t*)(smem + H_LO + off) = lp;
        v0 = fmaxf(fmaf(c[2], s0, b0v), 0.0f);
        v1 = fmaxf(fmaf(c[3], s1v, b1v), 0.0f);
        split2(v0, v1, hp, lp);
        off = (r0 + 8) * 528 + n * 2;
        *(uint32_t*)(smem + H_HI + off) = hp;
        *(uint32_t*)(smem + H_LO + off) = lp;
    }
    __syncthreads();

#pragma unroll
    for (int mt = 0; mt < 4; mt++)
#pragma unroll
        for (int nt = 0; nt < 8; nt++)
#pragma unroll
            for (int j = 0; j < 4; j++) acc[mt][nt][j] = 0.0f;

    // ================= LAYER 2: K=256, 8 chunks of 32 =================
#pragma unroll 1
    for (int kc = 0; kc < 8; kc++) {
        if (kc) __syncthreads();
        {
            const uint4* gh = (const uint4*)g_w2h;
            const uint4* gl = (const uint4*)g_w2l;
#pragma unroll
            for (int e = tid; e < 1024; e += 256) {
                int r = e >> 5, q = e & 31;
                uint32_t off = r * 528 + q * 16;
                *(uint4*)(smem + W_HI + off) = gh[(kc * 32 + r) * 32 + q];
                *(uint4*)(smem + W_LO + off) = gl[(kc * 32 + r) * 32 + q];
            }
        }
        __syncthreads();
#pragma unroll
        for (int kk = 0; kk < 2; kk++) {
            uint32_t bh[8][2], bl[8][2];
#pragma unroll
            for (int np = 0; np < 4; np++) {
                int n0 = wn * 64 + np * 16;
                uint32_t roff = (uint32_t)(kk * 16 + qmh + lrow) * 528 + (n0 + qkh) * 2;
                ldsm4t(bh[2 * np][0], bh[2 * np][1], bh[2 * np + 1][0], bh[2 * np + 1][1],
                       sb + W_HI + roff);
                ldsm4t(bl[2 * np][0], bl[2 * np][1], bl[2 * np + 1][0], bl[2 * np + 1][1],
                       sb + W_LO + roff);
            }
#pragma unroll
            for (int mt = 0; mt < 4; mt++) {
                int m0 = wm * 64 + mt * 16;
                uint32_t aoff = (uint32_t)(m0 + qmh + lrow) * 528 + (kc * 32 + kk * 16 + qkh) * 2;
                uint32_t ah[4], al[4];
                ldsm4(ah[0], ah[1], ah[2], ah[3], sb + H_HI + aoff);
                ldsm4(al[0], al[1], al[2], al[3], sb + H_LO + aoff);
#pragma unroll
                for (int nt = 0; nt < 8; nt++) {
                    mma16816(acc[mt][nt], ah, bh[nt]);
                    mma16816(acc[mt][nt], ah, bl[nt]);
                    mma16816(acc[mt][nt], al, bh[nt]);
                }
            }
        }
    }

    // ================= EPILOGUE 2: BN+ReLU -> fp32 out =================
#pragma unroll
    for (int mt = 0; mt < 4; mt++)
#pragma unroll
    for (int nt = 0; nt < 8; nt++) {
        int m0 = wm * 64 + mt * 16, n0 = wn * 64 + nt * 8;
        int r0 = m0 + (lane >> 2), n = n0 + 2 * (lane & 3);
        float s0 = s_s2[n], s1v = s_s2[n + 1], b0v = s_b2[n], b1v = s_b2[n + 1];
        float* c = acc[mt][nt];
        float2 o;
        o.x = fmaxf(fmaf(c[0], s0, b0v), 0.0f);
        o.y = fmaxf(fmaf(c[1], s1v, b1v), 0.0f);
        *(float2*)(out + (size_t)(row0 + r0) * HP + n) = o;
        o.x = fmaxf(fmaf(c[2], s0, b0v), 0.0f);
        o.y = fmaxf(fmaf(c[3], s1v, b1v), 0.0f);
        *(float2*)(out + (size_t)(row0 + r0 + 8) * HP + n) = o;
    }
}

// ---------------- launch ----------------
extern "C" void kernel_launch(void* const* d_in, const int* in_sizes, int n_in,
                              void* d_out, int out_size) {
    const float* xyz1    = (const float*)d_in[0];
    const float* xyz2    = (const float*)d_in[1];
    const float* points1 = (const float*)d_in[2];
    const float* points2 = (const float*)d_in[3];
    const float* W1      = (const float*)d_in[4];
    const float* gamma1  = (const float*)d_in[5];
    const float* beta1   = (const float*)d_in[6];
    const float* rm1     = (const float*)d_in[7];
    const float* rv1     = (const float*)d_in[8];
    const float* W2      = (const float*)d_in[9];
    const float* gamma2  = (const float*)d_in[10];
    const float* beta2   = (const float*)d_in[11];
    const float* rm2     = (const float*)d_in[12];
    const float* rv2     = (const float*)d_in[13];
    float* out = (float*)d_out;

    cudaFuncSetAttribute(mlp_kernel, cudaFuncAttributeMaxDynamicSharedMemorySize, SMEM_BYTES);

    prep_kernel<<<(K1P * HP + 255) / 256, 256>>>(W1, W2, gamma1, beta1, rm1, rv1,
                                                 gamma2, beta2, rm2, rv2);
    knn3_kernel<<<dim3(NP / 256, BB), 256>>>(xyz1, xyz2);
    mlp_kernel<<<MROWS / 128, 256, SMEM_BYTES>>>(points1, points2, out);
}